// round 1
// baseline (speedup 1.0000x reference)
#include <cuda_runtime.h>
#include <cstdint>

#define NQ 2048
#define NB 40000
#define NK 2048
#define ND 512
#define BK 32

// ---- scratch (device globals; no allocation allowed) ----
__device__ float g_c2[NK];
__device__ unsigned long long g_min[NB];
__device__ int g_idx[NB];
__device__ float g_sall[(size_t)NQ * NK];   // 16 MB: query @ codebook^T
__device__ float g_partial[320];

// ---- init: g_min = +inf-pack, c2[j] = ||codebook_j||^2 ----
__global__ void k_init(const float* __restrict__ cb) {
    int gid = blockIdx.x * 256 + threadIdx.x;
    if (gid < NB) g_min[gid] = 0xFFFFFFFFFFFFFFFFull;
    int w = gid >> 5;
    int lane = gid & 31;
    if (w < NK) {
        const float* r = cb + (size_t)w * ND;
        float s = 0.f;
        #pragma unroll
        for (int d = lane; d < ND; d += 32) { float v = r[d]; s += v * v; }
        #pragma unroll
        for (int o = 16; o > 0; o >>= 1) s += __shfl_xor_sync(0xffffffffu, s, o);
        if (lane == 0) g_c2[w] = s;
    }
}

// ---- distance GEMM (entity @ codebook^T) with fused argmin ----
// tile 128x128, BK=32, 256 threads, 8x8 per thread
__global__ __launch_bounds__(256)
void k_dist_argmin(const float* __restrict__ ent, const float* __restrict__ cb) {
    __shared__ float As[BK][132];
    __shared__ float Bs[BK][132];
    const int col0 = blockIdx.x * 128;   // codebook tile
    const int row0 = blockIdx.y * 128;   // entity tile
    const int tid = threadIdx.x;
    const int tcol = tid & 15;
    const int trow = tid >> 4;
    float acc[8][8] = {};

    for (int kk = 0; kk < ND; kk += BK) {
        #pragma unroll
        for (int it = 0; it < 4; it++) {
            int f4 = tid + it * 256;
            int r = f4 >> 3;
            int c = (f4 & 7) << 2;
            int gr = row0 + r;
            float4 v = make_float4(0.f, 0.f, 0.f, 0.f);
            if (gr < NB) v = *(const float4*)(ent + (size_t)gr * ND + kk + c);
            As[c + 0][r] = v.x; As[c + 1][r] = v.y; As[c + 2][r] = v.z; As[c + 3][r] = v.w;
            float4 w = *(const float4*)(cb + (size_t)(col0 + r) * ND + kk + c);
            Bs[c + 0][r] = w.x; Bs[c + 1][r] = w.y; Bs[c + 2][r] = w.z; Bs[c + 3][r] = w.w;
        }
        __syncthreads();
        #pragma unroll
        for (int k = 0; k < BK; k++) {
            float4 a0 = *(const float4*)&As[k][trow * 8];
            float4 a1 = *(const float4*)&As[k][trow * 8 + 4];
            float4 b0 = *(const float4*)&Bs[k][tcol * 8];
            float4 b1 = *(const float4*)&Bs[k][tcol * 8 + 4];
            float a[8] = {a0.x, a0.y, a0.z, a0.w, a1.x, a1.y, a1.z, a1.w};
            float b[8] = {b0.x, b0.y, b0.z, b0.w, b1.x, b1.y, b1.z, b1.w};
            #pragma unroll
            for (int i = 0; i < 8; i++)
                #pragma unroll
                for (int j = 0; j < 8; j++)
                    acc[i][j] = fmaf(a[i], b[j], acc[i][j]);
        }
        __syncthreads();
    }

    // epilogue: d = c2[j] - 2*dot (x^2 term is constant per row -> argmin-invariant)
    #pragma unroll
    for (int i = 0; i < 8; i++) {
        int gr = row0 + trow * 8 + i;
        float best = 3.4e38f;
        int bj = 0;
        #pragma unroll
        for (int j = 0; j < 8; j++) {
            int gc = col0 + tcol * 8 + j;
            float d = g_c2[gc] - 2.0f * acc[i][j];
            if (d < best) { best = d; bj = gc; }   // strict < keeps lowest index on ties
        }
        unsigned int kb = __float_as_uint(best);
        kb = (kb & 0x80000000u) ? ~kb : (kb | 0x80000000u);   // orderable float
        unsigned long long pack = ((unsigned long long)kb << 32) | (unsigned int)bj;
        // reduce across the 16 tcol lanes sharing this entity row (same half-warp)
        #pragma unroll
        for (int s = 1; s < 16; s <<= 1) {
            unsigned long long o = __shfl_xor_sync(0xffffffffu, pack, s);
            pack = (o < pack) ? o : pack;
        }
        if (tcol == 0 && gr < NB) atomicMin(&g_min[gr], pack);
    }
}

// ---- idx extraction ----
__global__ void k_extract(float* __restrict__ out) {
    int b = blockIdx.x * 256 + threadIdx.x;
    if (b < NB) {
        int j = (int)(unsigned int)(g_min[b] & 0xFFFFFFFFull);
        g_idx[b] = j;
        out[(size_t)NQ * NB + 1 + b] = (float)j;
    }
}

// ---- S_all = query @ codebook^T (2048x2048x512) ----
__global__ __launch_bounds__(256)
void k_sall(const float* __restrict__ qry, const float* __restrict__ cb) {
    __shared__ float As[BK][132];
    __shared__ float Bs[BK][132];
    const int col0 = blockIdx.x * 128;
    const int row0 = blockIdx.y * 128;
    const int tid = threadIdx.x;
    const int tcol = tid & 15;
    const int trow = tid >> 4;
    float acc[8][8] = {};

    for (int kk = 0; kk < ND; kk += BK) {
        #pragma unroll
        for (int it = 0; it < 4; it++) {
            int f4 = tid + it * 256;
            int r = f4 >> 3;
            int c = (f4 & 7) << 2;
            float4 v = *(const float4*)(qry + (size_t)(row0 + r) * ND + kk + c);
            As[c + 0][r] = v.x; As[c + 1][r] = v.y; As[c + 2][r] = v.z; As[c + 3][r] = v.w;
            float4 w = *(const float4*)(cb + (size_t)(col0 + r) * ND + kk + c);
            Bs[c + 0][r] = w.x; Bs[c + 1][r] = w.y; Bs[c + 2][r] = w.z; Bs[c + 3][r] = w.w;
        }
        __syncthreads();
        #pragma unroll
        for (int k = 0; k < BK; k++) {
            float4 a0 = *(const float4*)&As[k][trow * 8];
            float4 a1 = *(const float4*)&As[k][trow * 8 + 4];
            float4 b0 = *(const float4*)&Bs[k][tcol * 8];
            float4 b1 = *(const float4*)&Bs[k][tcol * 8 + 4];
            float a[8] = {a0.x, a0.y, a0.z, a0.w, a1.x, a1.y, a1.z, a1.w};
            float b[8] = {b0.x, b0.y, b0.z, b0.w, b1.x, b1.y, b1.z, b1.w};
            #pragma unroll
            for (int i = 0; i < 8; i++)
                #pragma unroll
                for (int j = 0; j < 8; j++)
                    acc[i][j] = fmaf(a[i], b[j], acc[i][j]);
        }
        __syncthreads();
    }
    #pragma unroll
    for (int i = 0; i < 8; i++) {
        size_t r = (size_t)(row0 + trow * 8 + i);
        float4 s0 = make_float4(acc[i][0], acc[i][1], acc[i][2], acc[i][3]);
        float4 s1 = make_float4(acc[i][4], acc[i][5], acc[i][6], acc[i][7]);
        *(float4*)(g_sall + r * NK + col0 + tcol * 8) = s0;
        *(float4*)(g_sall + r * NK + col0 + tcol * 8 + 4) = s1;
    }
}

// ---- vq_loss partials: sum (codebook[idx[b]] - ent[b])^2 ----
__global__ __launch_bounds__(256)
void k_loss_partial(const float* __restrict__ ent, const float* __restrict__ cb) {
    __shared__ float red[256];
    const int tid = threadIdx.x;
    const int b0 = blockIdx.x * 128;
    float s = 0.f;
    for (int e = 0; e < 128; e++) {
        int b = b0 + e;
        if (b >= NB) break;
        const float* x = ent + (size_t)b * ND;
        const float* c = cb + (size_t)g_idx[b] * ND;
        float d0 = x[tid] - c[tid];
        float d1 = x[tid + 256] - c[tid + 256];
        s += d0 * d0 + d1 * d1;
    }
    red[tid] = s;
    __syncthreads();
    for (int o = 128; o > 0; o >>= 1) {
        if (tid < o) red[tid] += red[tid + o];
        __syncthreads();
    }
    if (tid == 0) g_partial[blockIdx.x] = red[0];
}

__global__ void k_loss_final(float* __restrict__ out) {
    if (threadIdx.x == 0 && blockIdx.x == 0) {
        double t = 0.0;
        for (int i = 0; i < 313; i++) t += (double)g_partial[i];
        // mse(sg(q),x) + 0.25*mse(q,sg(x)) == 1.25 * mean((q-x)^2) numerically
        out[(size_t)NQ * NB] = (float)(1.25 * t / ((double)NB * (double)ND));
    }
}

// ---- score gather: score[q][b] = S_all[q][idx[b]], row staged in smem ----
#define GB_CHUNK 2048
#define GQ_CHUNK 128
__global__ __launch_bounds__(256)
void k_gather(float* __restrict__ out) {
    __shared__ float srow[NK];
    const int tid = threadIdx.x;
    const int b0 = blockIdx.x * GB_CHUNK;
    const int q0 = blockIdx.y * GQ_CHUNK;
    const int myb = b0 + tid * 8;
    int myidx[8];
    #pragma unroll
    for (int t = 0; t < 8; t++) myidx[t] = (myb + t < NB) ? g_idx[myb + t] : 0;

    for (int q = q0; q < q0 + GQ_CHUNK; q++) {
        __syncthreads();
        #pragma unroll
        for (int t = 0; t < 2; t++)
            ((float4*)srow)[tid + t * 256] =
                ((const float4*)(g_sall + (size_t)q * NK))[tid + t * 256];
        __syncthreads();
        if (myb + 7 < NB) {
            float4 v0 = make_float4(srow[myidx[0]], srow[myidx[1]], srow[myidx[2]], srow[myidx[3]]);
            float4 v1 = make_float4(srow[myidx[4]], srow[myidx[5]], srow[myidx[6]], srow[myidx[7]]);
            float* p = out + (size_t)q * NB + myb;
            *(float4*)p = v0;
            *(float4*)(p + 4) = v1;
        } else {
            for (int t = 0; t < 8; t++)
                if (myb + t < NB) out[(size_t)q * NB + myb + t] = srow[myidx[t]];
        }
    }
}

extern "C" void kernel_launch(void* const* d_in, const int* in_sizes, int n_in,
                              void* d_out, int out_size) {
    const float* qry = (const float*)d_in[0];   // (2048, 512)
    const float* ent = (const float*)d_in[1];   // (40000, 512)
    const float* cb  = (const float*)d_in[2];   // (2048, 512)
    float* out = (float*)d_out;                 // score (2048*40000) | vq_loss (1) | idx (40000)

    k_init<<<256, 256>>>(cb);
    k_dist_argmin<<<dim3(16, 313), 256>>>(ent, cb);
    k_extract<<<157, 256>>>(out);
    k_sall<<<dim3(16, 16), 256>>>(qry, cb);
    k_loss_partial<<<313, 256>>>(ent, cb);
    k_loss_final<<<1, 32>>>(out);
    k_gather<<<dim3(20, 16), 256>>>(out);
}

// round 3
// speedup vs baseline: 1.1289x; 1.1289x over previous
#include <cuda_runtime.h>
#include <cuda_fp16.h>
#include <cstdint>

#define NQ 2048
#define NB 40000
#define NK 2048
#define ND 512
#define BK 32

// ======================= device scratch (no allocation allowed) ==========
__device__ float g_c2[NK];
__device__ int g_idx[NB];
__device__ float g_sall[(size_t)NQ * NK];   // 16 MB
__device__ float g_partial[320];
__device__ int g_nflag;
__device__ int g_flag[2048];
// fp16 2-plane emulation storage
__device__ __half g_eh0[(size_t)NB * ND];
__device__ __half g_eh1[(size_t)NB * ND];
__device__ __half g_ch0[(size_t)NK * ND];
__device__ __half g_ch1[(size_t)NK * ND];

// ======================= helpers =========================================
__device__ __forceinline__ uint32_t smem_to_u32(const void* p) {
    uint32_t a;
    asm("{ .reg .u64 t; cvta.to.shared.u64 t, %1; cvt.u32.u64 %0, t; }" : "=r"(a) : "l"(p));
    return a;
}
__device__ __forceinline__ void ldsm4(uint32_t* d, uint32_t addr) {
    asm volatile("ldmatrix.sync.aligned.m8n8.x4.shared.b16 {%0,%1,%2,%3}, [%4];"
        : "=r"(d[0]), "=r"(d[1]), "=r"(d[2]), "=r"(d[3]) : "r"(addr));
}
__device__ __forceinline__ void mma16816(float* c, const uint32_t* a, const uint32_t* b) {
    asm volatile("mma.sync.aligned.m16n8k16.row.col.f32.f16.f16.f32 "
        "{%0,%1,%2,%3}, {%4,%5,%6,%7}, {%8,%9}, {%0,%1,%2,%3};"
        : "+f"(c[0]), "+f"(c[1]), "+f"(c[2]), "+f"(c[3])
        : "r"(a[0]), "r"(a[1]), "r"(a[2]), "r"(a[3]), "r"(b[0]), "r"(b[1]));
}

// ======================= fp32 -> 2x fp16 plane split =====================
__global__ void k_splith(const float* __restrict__ src, int n, int which) {
    int i = blockIdx.x * 256 + threadIdx.x;
    if (i >= n) return;
    float x = src[i];
    __half h0 = __float2half_rn(x);
    float r = x - __half2float(h0);
    __half h1 = __float2half_rn(r);
    if (which == 0) { g_eh0[i] = h0; g_eh1[i] = h1; }
    else            { g_ch0[i] = h0; g_ch1[i] = h1; }
}

// ======================= init: c2[j] = ||codebook_j||^2 ==================
__global__ void k_init(const float* __restrict__ cb) {
    int gid = blockIdx.x * 256 + threadIdx.x;
    if (gid == 0) g_nflag = 0;
    int w = gid >> 5;
    int lane = gid & 31;
    if (w < NK) {
        const float* r = cb + (size_t)w * ND;
        float s = 0.f;
        #pragma unroll
        for (int d = lane; d < ND; d += 32) { float v = r[d]; s += v * v; }
        #pragma unroll
        for (int o = 16; o > 0; o >>= 1) s += __shfl_xor_sync(0xffffffffu, s, o);
        if (lane == 0) g_c2[w] = s;
    }
}

// ======================= HMMA distance + fused argmin ====================
// 512 threads = 16 warps in 4(m) x 4(n) grid; CTA tile 128 rows x 128 cols.
// Warp tile m32 x n32 (am 0..1, an 0..3 atoms). 16 col-tiles looped per CTA.
// fp16 2-plane emulation: 3 products A0B0 + A0B1 + A1B0 per k16.
// smem: A0@0 A1@16K B0@32K B1@48K (each 128x64 half, SW128), c2s@64K.
#define DIST_SMEM (4 * 16384 + 1024)

struct __align__(16) F4 { float x, y, z, w; };

__global__ __launch_bounds__(512)
void k_dist(float* __restrict__ out) {
    extern __shared__ char smem[];
    const uint32_t sb = smem_to_u32(smem);
    float* c2s = (float*)(smem + 65536);
    const int tid = threadIdx.x;
    const int wid = tid >> 5, lane = tid & 31;
    const int warp_m = wid >> 2, warp_n = wid & 3;
    const int row0 = blockIdx.x * 128;
    const size_t arow0 = (size_t)row0 * ND;

    // ldmatrix per-lane constants
    const int a_row = lane & 15;
    const int a_c0 = (lane >> 4) * 16;
    const int a_xr = (a_row & 7) * 16;
    const int b_row = (lane & 7) + ((lane >> 4) << 3);
    const int b_c0 = ((lane >> 3) & 1) * 16;
    const int b_xr = (b_row & 7) * 16;
    uint32_t a_addr[2], b_addr[2];
    #pragma unroll
    for (int am = 0; am < 2; am++)
        a_addr[am] = sb + (uint32_t)((warp_m * 32 + am * 16 + a_row) * 128);
    #pragma unroll
    for (int bp = 0; bp < 2; bp++)
        b_addr[bp] = sb + 32768u + (uint32_t)((warp_n * 32 + bp * 16 + b_row) * 128);

    float best[4], best2[4]; int bidx[4];
    #pragma unroll
    for (int k = 0; k < 4; k++) { best[k] = 3.4e38f; best2[k] = 3.4e38f; bidx[k] = 0; }

    float4 pf[8];
    const float4 z4 = make_float4(0.f, 0.f, 0.f, 0.f);

    for (int nt = 0; nt < 16; nt++) {
        __syncthreads();   // prior epilogue done reading c2s
        if (tid < 128) c2s[tid] = g_c2[nt * 128 + tid];
        float acc[2][4][4];
        #pragma unroll
        for (int am = 0; am < 2; am++)
            #pragma unroll
            for (int an = 0; an < 4; an++)
                #pragma unroll
                for (int r = 0; r < 4; r++) acc[am][an][r] = 0.f;

        // prefetch kc=0
        {
            #pragma unroll
            for (int i = 0; i < 2; i++) {
                int idx = tid + i * 512;
                int r = idx >> 3, c16 = idx & 7;
                size_t aoff = arow0 + (size_t)r * ND + c16 * 8;
                if (row0 + r < NB) {
                    pf[i * 4 + 0] = *(const float4*)(g_eh0 + aoff);
                    pf[i * 4 + 1] = *(const float4*)(g_eh1 + aoff);
                } else { pf[i * 4 + 0] = z4; pf[i * 4 + 1] = z4; }
                size_t boff = (size_t)(nt * 128 + r) * ND + c16 * 8;
                pf[i * 4 + 2] = *(const float4*)(g_ch0 + boff);
                pf[i * 4 + 3] = *(const float4*)(g_ch1 + boff);
            }
        }

        for (int kc = 0; kc < 8; kc++) {
            __syncthreads();   // tiles free (previous mma done)
            #pragma unroll
            for (int i = 0; i < 2; i++) {
                int idx = tid + i * 512;
                int r = idx >> 3, c16 = idx & 7;
                uint32_t soff = (uint32_t)(r * 128 + ((c16 * 16) ^ ((r & 7) * 16)));
                *(float4*)(smem + soff)         = pf[i * 4 + 0];
                *(float4*)(smem + 16384 + soff) = pf[i * 4 + 1];
                *(float4*)(smem + 32768 + soff) = pf[i * 4 + 2];
                *(float4*)(smem + 49152 + soff) = pf[i * 4 + 3];
            }
            __syncthreads();
            if (kc < 7) {
                const int kkp = (kc + 1) * 64;
                #pragma unroll
                for (int i = 0; i < 2; i++) {
                    int idx = tid + i * 512;
                    int r = idx >> 3, c16 = idx & 7;
                    size_t aoff = arow0 + (size_t)r * ND + kkp + c16 * 8;
                    if (row0 + r < NB) {
                        pf[i * 4 + 0] = *(const float4*)(g_eh0 + aoff);
                        pf[i * 4 + 1] = *(const float4*)(g_eh1 + aoff);
                    } else { pf[i * 4 + 0] = z4; pf[i * 4 + 1] = z4; }
                    size_t boff = (size_t)(nt * 128 + r) * ND + kkp + c16 * 8;
                    pf[i * 4 + 2] = *(const float4*)(g_ch0 + boff);
                    pf[i * 4 + 3] = *(const float4*)(g_ch1 + boff);
                }
            }
            // ---- 4 k16 steps of 3-product emulated MMA ----
            #pragma unroll
            for (int kb = 0; kb < 4; kb++) {
                const uint32_t ca = (uint32_t)((a_c0 + kb * 32) ^ a_xr);
                const uint32_t cbo = (uint32_t)((b_c0 + kb * 32) ^ b_xr);
                uint32_t af[2][4], bf[4][2], bg[4][2];
                #pragma unroll
                for (int bp = 0; bp < 2; bp++) {
                    uint32_t t[4];
                    ldsm4(t, b_addr[bp] + cbo);
                    bf[bp * 2][0] = t[0]; bf[bp * 2][1] = t[1];
                    bf[bp * 2 + 1][0] = t[2]; bf[bp * 2 + 1][1] = t[3];
                }
                #pragma unroll
                for (int bp = 0; bp < 2; bp++) {
                    uint32_t t[4];
                    ldsm4(t, b_addr[bp] + 16384u + cbo);
                    bg[bp * 2][0] = t[0]; bg[bp * 2][1] = t[1];
                    bg[bp * 2 + 1][0] = t[2]; bg[bp * 2 + 1][1] = t[3];
                }
                #pragma unroll
                for (int am = 0; am < 2; am++) ldsm4(af[am], a_addr[am] + ca);
                #pragma unroll
                for (int am = 0; am < 2; am++)
                    #pragma unroll
                    for (int an = 0; an < 4; an++) mma16816(acc[am][an], af[am], bf[an]);
                #pragma unroll
                for (int am = 0; am < 2; am++)
                    #pragma unroll
                    for (int an = 0; an < 4; an++) mma16816(acc[am][an], af[am], bg[an]);
                #pragma unroll
                for (int am = 0; am < 2; am++) ldsm4(af[am], a_addr[am] + 16384u + ca);
                #pragma unroll
                for (int am = 0; am < 2; am++)
                    #pragma unroll
                    for (int an = 0; an < 4; an++) mma16816(acc[am][an], af[am], bf[an]);
            }
        }
        // ---- per-nt epilogue: fold into per-thread argmin tracking ----
        #pragma unroll
        for (int am = 0; am < 2; am++) {
            #pragma unroll
            for (int an = 0; an < 4; an++) {
                int cl = warp_n * 32 + an * 8 + (lane & 3) * 2;
                float c2a = c2s[cl], c2b = c2s[cl + 1];
                int gc = nt * 128 + cl;
                #pragma unroll
                for (int h = 0; h < 2; h++) {
                    int k = am * 2 + h;
                    float d0 = c2a - 2.f * acc[am][an][h * 2 + 0];
                    float d1 = c2b - 2.f * acc[am][an][h * 2 + 1];
                    if (d0 < best[k]) { best2[k] = best[k]; best[k] = d0; bidx[k] = gc; }
                    else if (d0 < best2[k]) best2[k] = d0;
                    if (d1 < best[k]) { best2[k] = best[k]; best[k] = d1; bidx[k] = gc + 1; }
                    else if (d1 < best2[k]) best2[k] = d1;
                }
            }
        }
    }

    // ---- final reduce: quad lanes -> smem -> per-row ----
    __syncthreads();
    float* sred1 = (float*)smem;
    float* sred2 = (float*)(smem + 2048);
    int*   sredi = (int*)(smem + 4096);
    #pragma unroll
    for (int k = 0; k < 4; k++) {
        float b1 = best[k], b2 = best2[k]; int ix = bidx[k];
        #pragma unroll
        for (int s = 1; s < 4; s <<= 1) {
            float o1 = __shfl_xor_sync(0xffffffffu, b1, s);
            float o2 = __shfl_xor_sync(0xffffffffu, b2, s);
            int oi = __shfl_xor_sync(0xffffffffu, ix, s);
            if (o1 < b1) { b2 = fminf(b1, o2); b1 = o1; ix = oi; }
            else b2 = fminf(b2, o1);
        }
        if ((lane & 3) == 0) {
            int rl = warp_m * 32 + (k >> 1) * 16 + (k & 1) * 8 + (lane >> 2);
            sred1[rl * 4 + warp_n] = b1;
            sred2[rl * 4 + warp_n] = b2;
            sredi[rl * 4 + warp_n] = ix;
        }
    }
    __syncthreads();
    if (tid < 128) {
        float b1 = sred1[tid * 4], b2 = sred2[tid * 4];
        int ix = sredi[tid * 4];
        #pragma unroll
        for (int w = 1; w < 4; w++) {
            float o1 = sred1[tid * 4 + w], o2 = sred2[tid * 4 + w];
            int oi = sredi[tid * 4 + w];
            if (o1 < b1) { b2 = fminf(b1, o2); b1 = o1; ix = oi; }
            else b2 = fminf(b2, o1);
        }
        int row = row0 + tid;
        if (row < NB) {
            g_idx[row] = ix;
            out[(size_t)NQ * NB + 1 + row] = (float)ix;
            if (b2 - b1 < 0.01f) {
                int s = atomicAdd(&g_nflag, 1);
                if (s < 2048) g_flag[s] = row;
            }
        }
    }
}

// ======================= exact fp32 repair for near-ties =================
__global__ __launch_bounds__(256)
void k_repair(const float* __restrict__ ent, const float* __restrict__ cb,
              float* __restrict__ out) {
    __shared__ float sx[ND];
    __shared__ unsigned long long red[256];
    const int tid = threadIdx.x;
    int n = g_nflag;
    if (n > 2048) n = 2048;
    for (int f = blockIdx.x; f < n; f += gridDim.x) {
        const int b = g_flag[f];
        sx[tid] = ent[(size_t)b * ND + tid];
        sx[tid + 256] = ent[(size_t)b * ND + tid + 256];
        __syncthreads();
        float best = 3.4e38f;
        int bj = 0;
        const int j0 = tid * 8;
        for (int jj = 0; jj < 8; jj++) {
            const int j = j0 + jj;
            const float* c = cb + (size_t)j * ND;
            float dot = 0.f;
            #pragma unroll 8
            for (int d = 0; d < ND; d++) dot = fmaf(sx[d], c[d], dot);
            float d2 = g_c2[j] - 2.0f * dot;
            if (d2 < best) { best = d2; bj = j; }
        }
        unsigned int kb = __float_as_uint(best);
        kb = (kb & 0x80000000u) ? ~kb : (kb | 0x80000000u);
        red[tid] = ((unsigned long long)kb << 32) | (unsigned int)bj;
        __syncthreads();
        for (int o = 128; o > 0; o >>= 1) {
            if (tid < o) { unsigned long long v = red[tid + o]; if (v < red[tid]) red[tid] = v; }
            __syncthreads();
        }
        if (tid == 0) {
            int j = (int)(unsigned int)(red[0] & 0xFFFFFFFFull);
            g_idx[b] = j;
            out[(size_t)NQ * NB + 1 + b] = (float)j;
        }
        __syncthreads();
    }
}

// ======================= S_all = query @ codebook^T (fp32 SIMT) ==========
__global__ __launch_bounds__(256)
void k_sall(const float* __restrict__ qry, const float* __restrict__ cb) {
    __shared__ float As[BK][132];
    __shared__ float Bs[BK][132];
    const int col0 = blockIdx.x * 128;
    const int row0 = blockIdx.y * 128;
    const int tid = threadIdx.x;
    const int tcol = tid & 15;
    const int trow = tid >> 4;
    float acc[8][8] = {};

    for (int kk = 0; kk < ND; kk += BK) {
        #pragma unroll
        for (int it = 0; it < 4; it++) {
            int f4 = tid + it * 256;
            int r = f4 >> 3;
            int c = (f4 & 7) << 2;
            float4 v = *(const float4*)(qry + (size_t)(row0 + r) * ND + kk + c);
            As[c + 0][r] = v.x; As[c + 1][r] = v.y; As[c + 2][r] = v.z; As[c + 3][r] = v.w;
            float4 w = *(const float4*)(cb + (size_t)(col0 + r) * ND + kk + c);
            Bs[c + 0][r] = w.x; Bs[c + 1][r] = w.y; Bs[c + 2][r] = w.z; Bs[c + 3][r] = w.w;
        }
        __syncthreads();
        #pragma unroll
        for (int k = 0; k < BK; k++) {
            float4 a0 = *(const float4*)&As[k][trow * 8];
            float4 a1 = *(const float4*)&As[k][trow * 8 + 4];
            float4 b0 = *(const float4*)&Bs[k][tcol * 8];
            float4 b1 = *(const float4*)&Bs[k][tcol * 8 + 4];
            float a[8] = {a0.x, a0.y, a0.z, a0.w, a1.x, a1.y, a1.z, a1.w};
            float b[8] = {b0.x, b0.y, b0.z, b0.w, b1.x, b1.y, b1.z, b1.w};
            #pragma unroll
            for (int i = 0; i < 8; i++)
                #pragma unroll
                for (int j = 0; j < 8; j++)
                    acc[i][j] = fmaf(a[i], b[j], acc[i][j]);
        }
        __syncthreads();
    }
    #pragma unroll
    for (int i = 0; i < 8; i++) {
        size_t r = (size_t)(row0 + trow * 8 + i);
        float4 s0 = make_float4(acc[i][0], acc[i][1], acc[i][2], acc[i][3]);
        float4 s1 = make_float4(acc[i][4], acc[i][5], acc[i][6], acc[i][7]);
        *(float4*)(g_sall + r * NK + col0 + tcol * 8) = s0;
        *(float4*)(g_sall + r * NK + col0 + tcol * 8 + 4) = s1;
    }
}

// ======================= vq_loss =========================================
__global__ __launch_bounds__(256)
void k_loss_partial(const float* __restrict__ ent, const float* __restrict__ cb) {
    __shared__ float red[256];
    const int tid = threadIdx.x;
    const int b0 = blockIdx.x * 128;
    float s = 0.f;
    for (int e = 0; e < 128; e++) {
        int b = b0 + e;
        if (b >= NB) break;
        const float* x = ent + (size_t)b * ND;
        const float* c = cb + (size_t)g_idx[b] * ND;
        float d0 = x[tid] - c[tid];
        float d1 = x[tid + 256] - c[tid + 256];
        s += d0 * d0 + d1 * d1;
    }
    red[tid] = s;
    __syncthreads();
    for (int o = 128; o > 0; o >>= 1) {
        if (tid < o) red[tid] += red[tid + o];
        __syncthreads();
    }
    if (tid == 0) g_partial[blockIdx.x] = red[0];
}

__global__ void k_loss_final(float* __restrict__ out) {
    if (threadIdx.x == 0 && blockIdx.x == 0) {
        double t = 0.0;
        for (int i = 0; i < 313; i++) t += (double)g_partial[i];
        out[(size_t)NQ * NB] = (float)(1.25 * t / ((double)NB * (double)ND));
    }
}

// ======================= score gather ====================================
#define GB_CHUNK 2048
#define GQ_CHUNK 128
__global__ __launch_bounds__(256)
void k_gather(float* __restrict__ out) {
    __shared__ float srow[NK];
    const int tid = threadIdx.x;
    const int b0 = blockIdx.x * GB_CHUNK;
    const int q0 = blockIdx.y * GQ_CHUNK;
    const int myb = b0 + tid * 8;
    int myidx[8];
    #pragma unroll
    for (int t = 0; t < 8; t++) myidx[t] = (myb + t < NB) ? g_idx[myb + t] : 0;

    for (int q = q0; q < q0 + GQ_CHUNK; q++) {
        __syncthreads();
        #pragma unroll
        for (int t = 0; t < 2; t++)
            ((float4*)srow)[tid + t * 256] =
                ((const float4*)(g_sall + (size_t)q * NK))[tid + t * 256];
        __syncthreads();
        if (myb + 7 < NB) {
            float4 v0 = make_float4(srow[myidx[0]], srow[myidx[1]], srow[myidx[2]], srow[myidx[3]]);
            float4 v1 = make_float4(srow[myidx[4]], srow[myidx[5]], srow[myidx[6]], srow[myidx[7]]);
            float* p = out + (size_t)q * NB + myb;
            *(float4*)p = v0;
            *(float4*)(p + 4) = v1;
        } else {
            for (int t = 0; t < 8; t++)
                if (myb + t < NB) out[(size_t)q * NB + myb + t] = srow[myidx[t]];
        }
    }
}

// ======================= launch ==========================================
extern "C" void kernel_launch(void* const* d_in, const int* in_sizes, int n_in,
                              void* d_out, int out_size) {
    const float* qry = (const float*)d_in[0];   // (2048, 512)
    const float* ent = (const float*)d_in[1];   // (40000, 512)
    const float* cb  = (const float*)d_in[2];   // (2048, 512)
    float* out = (float*)d_out;                 // score | vq_loss | idx

    cudaFuncSetAttribute(k_dist, cudaFuncAttributeMaxDynamicSharedMemorySize, DIST_SMEM);

    k_splith<<<(NB * ND + 255) / 256, 256>>>(ent, NB * ND, 0);
    k_splith<<<(NK * ND + 255) / 256, 256>>>(cb, NK * ND, 1);
    k_init<<<256, 256>>>(cb);
    k_dist<<<313, 512, DIST_SMEM>>>(out);
    k_repair<<<64, 256>>>(ent, cb, out);
    k_sall<<<dim3(16, 16), 256>>>(qry, cb);
    k_loss_partial<<<313, 256>>>(ent, cb);
    k_loss_final<<<1, 32>>>(out);
    k_gather<<<dim3(20, 16), 256>>>(out);
}

// round 4
// speedup vs baseline: 1.2624x; 1.1182x over previous
#include <cuda_runtime.h>
#include <cuda_fp16.h>
#include <cstdint>

#define NQ 2048
#define NB 40000
#define NK 2048
#define ND 512

// ======================= device scratch (no allocation allowed) ==========
__device__ float g_c2[NK];
__device__ float g_x2[NB];
__device__ float g_bestd[NB];
__device__ int g_idx[NB];
__device__ __align__(16) float g_sall[(size_t)NQ * NK];   // 16 MB
__device__ int g_nflag;
__device__ int g_flag[4096];
// fp16 2-plane emulation storage
__device__ __half g_eh0[(size_t)NB * ND];
__device__ __half g_eh1[(size_t)NB * ND];
__device__ __half g_ch0[(size_t)NK * ND];
__device__ __half g_ch1[(size_t)NK * ND];
__device__ __half g_qh0[(size_t)NQ * ND];
__device__ __half g_qh1[(size_t)NQ * ND];

// ======================= helpers =========================================
__device__ __forceinline__ uint32_t smem_to_u32(const void* p) {
    uint32_t a;
    asm("{ .reg .u64 t; cvta.to.shared.u64 t, %1; cvt.u32.u64 %0, t; }" : "=r"(a) : "l"(p));
    return a;
}
__device__ __forceinline__ void ldsm4(uint32_t* d, uint32_t addr) {
    asm volatile("ldmatrix.sync.aligned.m8n8.x4.shared.b16 {%0,%1,%2,%3}, [%4];"
        : "=r"(d[0]), "=r"(d[1]), "=r"(d[2]), "=r"(d[3]) : "r"(addr));
}
__device__ __forceinline__ void mma16816(float* c, const uint32_t* a, const uint32_t* b) {
    asm volatile("mma.sync.aligned.m16n8k16.row.col.f32.f16.f16.f32 "
        "{%0,%1,%2,%3}, {%4,%5,%6,%7}, {%8,%9}, {%0,%1,%2,%3};"
        : "+f"(c[0]), "+f"(c[1]), "+f"(c[2]), "+f"(c[3])
        : "r"(a[0]), "r"(a[1]), "r"(a[2]), "r"(a[3]), "r"(b[0]), "r"(b[1]));
}
__device__ __forceinline__ void cpa16(uint32_t dst, const void* src, bool ok) {
    int sz = ok ? 16 : 0;
    asm volatile("cp.async.cg.shared.global [%0], [%1], 16, %2;"
        :: "r"(dst), "l"(src), "r"(sz));
}
#define CPA_COMMIT() asm volatile("cp.async.commit_group;" ::: "memory")
#define CPA_WAIT2()  asm volatile("cp.async.wait_group 2;" ::: "memory")

// ======================= fused row split + norms =========================
// warp per row: fp32 -> (h0, h1) planes; which 0=entity(+x2) 1=codebook(+c2) 2=query
__global__ void k_splitrow(const float* __restrict__ src, int nrows, int which) {
    int gw = (blockIdx.x * 256 + threadIdx.x) >> 5;
    int lane = threadIdx.x & 31;
    if (which == 1 && gw == 0 && lane == 0) g_nflag = 0;
    if (gw >= nrows) return;
    const float* row = src + (size_t)gw * ND;
    __half *h0, *h1;
    if (which == 0) { h0 = g_eh0; h1 = g_eh1; }
    else if (which == 1) { h0 = g_ch0; h1 = g_ch1; }
    else { h0 = g_qh0; h1 = g_qh1; }
    float s = 0.f;
    #pragma unroll
    for (int j = 0; j < 4; j++) {
        int d = lane * 4 + j * 128;
        float4 v = *(const float4*)(row + d);
        __half a0 = __float2half_rn(v.x), a1 = __float2half_rn(v.y);
        __half a2 = __float2half_rn(v.z), a3 = __float2half_rn(v.w);
        __half b0 = __float2half_rn(v.x - __half2float(a0));
        __half b1 = __float2half_rn(v.y - __half2float(a1));
        __half b2 = __float2half_rn(v.z - __half2float(a2));
        __half b3 = __float2half_rn(v.w - __half2float(a3));
        __half2* p0 = (__half2*)(h0 + (size_t)gw * ND + d);
        __half2* p1 = (__half2*)(h1 + (size_t)gw * ND + d);
        p0[0] = __halves2half2(a0, a1); p0[1] = __halves2half2(a2, a3);
        p1[0] = __halves2half2(b0, b1); p1[1] = __halves2half2(b2, b3);
        s += v.x * v.x + v.y * v.y + v.z * v.z + v.w * v.w;
    }
    #pragma unroll
    for (int o = 16; o > 0; o >>= 1) s += __shfl_xor_sync(0xffffffffu, s, o);
    if (lane == 0) {
        if (which == 0) g_x2[gw] = s;
        else if (which == 1) g_c2[gw] = s;
    }
}

// ======================= HMMA distance + fused argmin ====================
// 512 threads = 16 warps (4m x 4n), warp tile m32n32, CTA 128 rows x 128 cols,
// 16 col-tiles x 8 K-chunks = 128 pipeline steps, 3-stage cp.async.
#define DIST_SMEM (3 * 65536)

__device__ __forceinline__ void dist_issue(uint32_t sb, int step, int row0, size_t arow0) {
    const int nt = step >> 3, kc = step & 7;
    const uint32_t base = sb + (uint32_t)(step % 3) * 65536u;
    const int tid = threadIdx.x;
    #pragma unroll
    for (int i = 0; i < 2; i++) {
        int idx = tid + i * 512;
        int r = idx >> 3, c16 = idx & 7;
        uint32_t soff = (uint32_t)(r * 128 + ((c16 * 16) ^ ((r & 7) * 16)));
        size_t aoff = arow0 + (size_t)r * ND + kc * 64 + c16 * 8;
        bool aok = (row0 + r) < NB;
        cpa16(base + soff,          g_eh0 + aoff, aok);
        cpa16(base + 16384u + soff, g_eh1 + aoff, aok);
        size_t boff = (size_t)(nt * 128 + r) * ND + kc * 64 + c16 * 8;
        cpa16(base + 32768u + soff, g_ch0 + boff, true);
        cpa16(base + 49152u + soff, g_ch1 + boff, true);
    }
}

__global__ __launch_bounds__(512)
void k_dist(float* __restrict__ out) {
    extern __shared__ char smem[];
    const uint32_t sb = smem_to_u32(smem);
    const int tid = threadIdx.x;
    const int wid = tid >> 5, lane = tid & 31;
    const int warp_m = wid >> 2, warp_n = wid & 3;
    const int row0 = blockIdx.x * 128;
    const size_t arow0 = (size_t)row0 * ND;

    const int a_row = lane & 15;
    const int a_c0 = (lane >> 4) * 16;
    const int a_xr = (a_row & 7) * 16;
    const int b_row = (lane & 7) + ((lane >> 4) << 3);
    const int b_c0 = ((lane >> 3) & 1) * 16;
    const int b_xr = (b_row & 7) * 16;
    uint32_t a_off[2], b_off[2];
    #pragma unroll
    for (int am = 0; am < 2; am++)
        a_off[am] = (uint32_t)((warp_m * 32 + am * 16 + a_row) * 128);
    #pragma unroll
    for (int bp = 0; bp < 2; bp++)
        b_off[bp] = 32768u + (uint32_t)((warp_n * 32 + bp * 16 + b_row) * 128);

    float best[4], best2[4]; int bidx[4];
    #pragma unroll
    for (int k = 0; k < 4; k++) { best[k] = 3.4e38f; best2[k] = 3.4e38f; bidx[k] = 0; }

    float acc[2][4][4];

    dist_issue(sb, 0, row0, arow0); CPA_COMMIT();
    dist_issue(sb, 1, row0, arow0); CPA_COMMIT();

    for (int s = 0; s < 128; s++) {
        const int nt = s >> 3, kc = s & 7;
        if (s + 2 < 128) dist_issue(sb, s + 2, row0, arow0);
        CPA_COMMIT();
        CPA_WAIT2();
        __syncthreads();
        if (kc == 0) {
            #pragma unroll
            for (int am = 0; am < 2; am++)
                #pragma unroll
                for (int an = 0; an < 4; an++)
                    #pragma unroll
                    for (int r = 0; r < 4; r++) acc[am][an][r] = 0.f;
        }
        const uint32_t base = sb + (uint32_t)(s % 3) * 65536u;
        #pragma unroll
        for (int kb = 0; kb < 4; kb++) {
            const uint32_t ca = (uint32_t)((a_c0 + kb * 32) ^ a_xr);
            const uint32_t cbo = (uint32_t)((b_c0 + kb * 32) ^ b_xr);
            uint32_t af[2][4], bf[4][2], bg[4][2];
            #pragma unroll
            for (int bp = 0; bp < 2; bp++) {
                uint32_t t[4];
                ldsm4(t, base + b_off[bp] + cbo);
                bf[bp * 2][0] = t[0]; bf[bp * 2][1] = t[1];
                bf[bp * 2 + 1][0] = t[2]; bf[bp * 2 + 1][1] = t[3];
            }
            #pragma unroll
            for (int bp = 0; bp < 2; bp++) {
                uint32_t t[4];
                ldsm4(t, base + b_off[bp] + 16384u + cbo);
                bg[bp * 2][0] = t[0]; bg[bp * 2][1] = t[1];
                bg[bp * 2 + 1][0] = t[2]; bg[bp * 2 + 1][1] = t[3];
            }
            #pragma unroll
            for (int am = 0; am < 2; am++) ldsm4(af[am], base + a_off[am] + ca);
            #pragma unroll
            for (int am = 0; am < 2; am++)
                #pragma unroll
                for (int an = 0; an < 4; an++) mma16816(acc[am][an], af[am], bf[an]);
            #pragma unroll
            for (int am = 0; am < 2; am++)
                #pragma unroll
                for (int an = 0; an < 4; an++) mma16816(acc[am][an], af[am], bg[an]);
            #pragma unroll
            for (int am = 0; am < 2; am++) ldsm4(af[am], base + a_off[am] + 16384u + ca);
            #pragma unroll
            for (int am = 0; am < 2; am++)
                #pragma unroll
                for (int an = 0; an < 4; an++) mma16816(acc[am][an], af[am], bf[an]);
        }
        if (kc == 7) {
            #pragma unroll
            for (int am = 0; am < 2; am++) {
                #pragma unroll
                for (int an = 0; an < 4; an++) {
                    int cl = warp_n * 32 + an * 8 + (lane & 3) * 2;
                    float c2a = __ldg(&g_c2[nt * 128 + cl]);
                    float c2b = __ldg(&g_c2[nt * 128 + cl + 1]);
                    int gc = nt * 128 + cl;
                    #pragma unroll
                    for (int h = 0; h < 2; h++) {
                        int k = am * 2 + h;
                        float d0 = c2a - 2.f * acc[am][an][h * 2 + 0];
                        float d1 = c2b - 2.f * acc[am][an][h * 2 + 1];
                        if (d0 < best[k]) { best2[k] = best[k]; best[k] = d0; bidx[k] = gc; }
                        else if (d0 < best2[k]) best2[k] = d0;
                        if (d1 < best[k]) { best2[k] = best[k]; best[k] = d1; bidx[k] = gc + 1; }
                        else if (d1 < best2[k]) best2[k] = d1;
                    }
                }
            }
        }
        __syncthreads();
    }

    // ---- final reduce: quad lanes -> smem -> per-row ----
    float* sred1 = (float*)smem;
    float* sred2 = (float*)(smem + 2048);
    int*   sredi = (int*)(smem + 4096);
    #pragma unroll
    for (int k = 0; k < 4; k++) {
        float b1 = best[k], b2 = best2[k]; int ix = bidx[k];
        #pragma unroll
        for (int s = 1; s < 4; s <<= 1) {
            float o1 = __shfl_xor_sync(0xffffffffu, b1, s);
            float o2 = __shfl_xor_sync(0xffffffffu, b2, s);
            int oi = __shfl_xor_sync(0xffffffffu, ix, s);
            if (o1 < b1) { b2 = fminf(b1, o2); b1 = o1; ix = oi; }
            else b2 = fminf(b2, o1);
        }
        if ((lane & 3) == 0) {
            int rl = warp_m * 32 + (k >> 1) * 16 + (k & 1) * 8 + (lane >> 2);
            sred1[rl * 4 + warp_n] = b1;
            sred2[rl * 4 + warp_n] = b2;
            sredi[rl * 4 + warp_n] = ix;
        }
    }
    __syncthreads();
    if (tid < 128) {
        float b1 = sred1[tid * 4], b2 = sred2[tid * 4];
        int ix = sredi[tid * 4];
        #pragma unroll
        for (int w = 1; w < 4; w++) {
            float o1 = sred1[tid * 4 + w], o2 = sred2[tid * 4 + w];
            int oi = sredi[tid * 4 + w];
            if (o1 < b1) { b2 = fminf(b1, o2); b1 = o1; ix = oi; }
            else b2 = fminf(b2, o1);
        }
        int row = row0 + tid;
        if (row < NB) {
            g_idx[row] = ix;
            g_bestd[row] = b1;
            out[(size_t)NQ * NB + 1 + row] = (float)ix;
            if (b2 - b1 < 0.01f) {
                int s = atomicAdd(&g_nflag, 1);
                if (s < 4096) g_flag[s] = row;
            }
        }
    }
}

// ======================= exact fp32 repair for near-ties =================
__global__ __launch_bounds__(256)
void k_repair(const float* __restrict__ ent, const float* __restrict__ cb,
              float* __restrict__ out) {
    __shared__ float sx[ND];
    __shared__ unsigned long long red[256];
    const int tid = threadIdx.x;
    int n = g_nflag;
    if (n > 4096) n = 4096;
    for (int f = blockIdx.x; f < n; f += gridDim.x) {
        const int b = g_flag[f];
        sx[tid] = ent[(size_t)b * ND + tid];
        sx[tid + 256] = ent[(size_t)b * ND + tid + 256];
        __syncthreads();
        float best = 3.4e38f;
        int bj = 0;
        const int j0 = tid * 8;
        for (int jj = 0; jj < 8; jj++) {
            const int j = j0 + jj;
            const float* c = cb + (size_t)j * ND;
            float dot = 0.f;
            #pragma unroll 8
            for (int d = 0; d < ND; d++) dot = fmaf(sx[d], c[d], dot);
            float d2 = g_c2[j] - 2.0f * dot;
            if (d2 < best) { best = d2; bj = j; }
        }
        unsigned int kb = __float_as_uint(best);
        kb = (kb & 0x80000000u) ? ~kb : (kb | 0x80000000u);
        red[tid] = ((unsigned long long)kb << 32) | (unsigned int)bj;
        __syncthreads();
        for (int o = 128; o > 0; o >>= 1) {
            if (tid < o) { unsigned long long v = red[tid + o]; if (v < red[tid]) red[tid] = v; }
            __syncthreads();
        }
        if (tid == 0) {
            unsigned long long w = red[0];
            int j = (int)(unsigned int)(w & 0xFFFFFFFFull);
            unsigned int kk = (unsigned int)(w >> 32);
            unsigned int fb = (kk & 0x80000000u) ? (kk & 0x7FFFFFFFu) : ~kk;
            g_idx[b] = j;
            g_bestd[b] = __uint_as_float(fb);
            out[(size_t)NQ * NB + 1 + b] = (float)j;
        }
        __syncthreads();
    }
}

// ======================= S_all = query @ codebook^T (HMMA) ===============
__device__ __forceinline__ void sall_issue(uint32_t sb, int step, size_t qrow0, size_t crow0) {
    const int kc = step;
    const uint32_t base = sb + (uint32_t)(step % 3) * 65536u;
    const int tid = threadIdx.x;
    #pragma unroll
    for (int i = 0; i < 2; i++) {
        int idx = tid + i * 512;
        int r = idx >> 3, c16 = idx & 7;
        uint32_t soff = (uint32_t)(r * 128 + ((c16 * 16) ^ ((r & 7) * 16)));
        size_t aoff = qrow0 + (size_t)r * ND + kc * 64 + c16 * 8;
        cpa16(base + soff,          g_qh0 + aoff, true);
        cpa16(base + 16384u + soff, g_qh1 + aoff, true);
        size_t boff = crow0 + (size_t)r * ND + kc * 64 + c16 * 8;
        cpa16(base + 32768u + soff, g_ch0 + boff, true);
        cpa16(base + 49152u + soff, g_ch1 + boff, true);
    }
}

__global__ __launch_bounds__(512)
void k_sall() {
    extern __shared__ char smem[];
    const uint32_t sb = smem_to_u32(smem);
    const int tid = threadIdx.x;
    const int wid = tid >> 5, lane = tid & 31;
    const int warp_m = wid >> 2, warp_n = wid & 3;
    const int col0 = blockIdx.x * 128;
    const int row0 = blockIdx.y * 128;
    const size_t qrow0 = (size_t)row0 * ND;
    const size_t crow0 = (size_t)col0 * ND;

    const int a_row = lane & 15;
    const int a_c0 = (lane >> 4) * 16;
    const int a_xr = (a_row & 7) * 16;
    const int b_row = (lane & 7) + ((lane >> 4) << 3);
    const int b_c0 = ((lane >> 3) & 1) * 16;
    const int b_xr = (b_row & 7) * 16;
    uint32_t a_off[2], b_off[2];
    #pragma unroll
    for (int am = 0; am < 2; am++)
        a_off[am] = (uint32_t)((warp_m * 32 + am * 16 + a_row) * 128);
    #pragma unroll
    for (int bp = 0; bp < 2; bp++)
        b_off[bp] = 32768u + (uint32_t)((warp_n * 32 + bp * 16 + b_row) * 128);

    float acc[2][4][4];
    #pragma unroll
    for (int am = 0; am < 2; am++)
        #pragma unroll
        for (int an = 0; an < 4; an++)
            #pragma unroll
            for (int r = 0; r < 4; r++) acc[am][an][r] = 0.f;

    sall_issue(sb, 0, qrow0, crow0); CPA_COMMIT();
    sall_issue(sb, 1, qrow0, crow0); CPA_COMMIT();

    for (int s = 0; s < 8; s++) {
        if (s + 2 < 8) sall_issue(sb, s + 2, qrow0, crow0);
        CPA_COMMIT();
        CPA_WAIT2();
        __syncthreads();
        const uint32_t base = sb + (uint32_t)(s % 3) * 65536u;
        #pragma unroll
        for (int kb = 0; kb < 4; kb++) {
            const uint32_t ca = (uint32_t)((a_c0 + kb * 32) ^ a_xr);
            const uint32_t cbo = (uint32_t)((b_c0 + kb * 32) ^ b_xr);
            uint32_t af[2][4], bf[4][2], bg[4][2];
            #pragma unroll
            for (int bp = 0; bp < 2; bp++) {
                uint32_t t[4];
                ldsm4(t, base + b_off[bp] + cbo);
                bf[bp * 2][0] = t[0]; bf[bp * 2][1] = t[1];
                bf[bp * 2 + 1][0] = t[2]; bf[bp * 2 + 1][1] = t[3];
            }
            #pragma unroll
            for (int bp = 0; bp < 2; bp++) {
                uint32_t t[4];
                ldsm4(t, base + b_off[bp] + 16384u + cbo);
                bg[bp * 2][0] = t[0]; bg[bp * 2][1] = t[1];
                bg[bp * 2 + 1][0] = t[2]; bg[bp * 2 + 1][1] = t[3];
            }
            #pragma unroll
            for (int am = 0; am < 2; am++) ldsm4(af[am], base + a_off[am] + ca);
            #pragma unroll
            for (int am = 0; am < 2; am++)
                #pragma unroll
                for (int an = 0; an < 4; an++) mma16816(acc[am][an], af[am], bf[an]);
            #pragma unroll
            for (int am = 0; am < 2; am++)
                #pragma unroll
                for (int an = 0; an < 4; an++) mma16816(acc[am][an], af[am], bg[an]);
            #pragma unroll
            for (int am = 0; am < 2; am++) ldsm4(af[am], base + a_off[am] + 16384u + ca);
            #pragma unroll
            for (int am = 0; am < 2; am++)
                #pragma unroll
                for (int an = 0; an < 4; an++) mma16816(acc[am][an], af[am], bf[an]);
        }
        __syncthreads();
    }

    #pragma unroll
    for (int am = 0; am < 2; am++)
        #pragma unroll
        for (int h = 0; h < 2; h++) {
            int r = row0 + warp_m * 32 + am * 16 + h * 8 + (lane >> 2);
            #pragma unroll
            for (int an = 0; an < 4; an++) {
                int c = col0 + warp_n * 32 + an * 8 + (lane & 3) * 2;
                *(float2*)(g_sall + (size_t)r * NK + c) =
                    make_float2(acc[am][an][h * 2], acc[am][an][h * 2 + 1]);
            }
        }
}

// ======================= vq_loss: mean(x2 + bestd) * 1.25 ================
__global__ void k_loss_final(float* __restrict__ out) {
    __shared__ double sred[256];
    const int tid = threadIdx.x;
    double s = 0.0;
    for (int b = tid; b < NB; b += 256) s += (double)g_x2[b] + (double)g_bestd[b];
    sred[tid] = s;
    __syncthreads();
    for (int o = 128; o > 0; o >>= 1) {
        if (tid < o) sred[tid] += sred[tid + o];
        __syncthreads();
    }
    if (tid == 0) out[(size_t)NQ * NB] = (float)(1.25 * sred[0] / ((double)NB * (double)ND));
}

// ======================= score gather ====================================
// 128 blocks x 16 query rows; idx read once per 8-entity group.
#define QCH 16
#define GATHER_SMEM (QCH * NK * 4)
__global__ __launch_bounds__(512)
void k_gather(float* __restrict__ out) {
    extern __shared__ float srow[];   // [QCH][NK]
    const int tid = threadIdx.x;
    const int q0 = blockIdx.x * QCH;
    for (int i = tid; i < QCH * NK / 4; i += 512)
        ((float4*)srow)[i] = ((const float4*)(g_sall + (size_t)q0 * NK))[i];
    __syncthreads();
    for (int c = 0; c < 10; c++) {
        int b = c * 4096 + tid * 8;
        if (b >= NB) continue;
        int idx8[8];
        #pragma unroll
        for (int t = 0; t < 8; t++) idx8[t] = g_idx[b + t];
        #pragma unroll
        for (int q = 0; q < QCH; q++) {
            const float* r = srow + q * NK;
            float4 v0 = make_float4(r[idx8[0]], r[idx8[1]], r[idx8[2]], r[idx8[3]]);
            float4 v1 = make_float4(r[idx8[4]], r[idx8[5]], r[idx8[6]], r[idx8[7]]);
            float* p = out + (size_t)(q0 + q) * NB + b;
            *(float4*)p = v0;
            *(float4*)(p + 4) = v1;
        }
    }
}

// ======================= launch ==========================================
extern "C" void kernel_launch(void* const* d_in, const int* in_sizes, int n_in,
                              void* d_out, int out_size) {
    const float* qry = (const float*)d_in[0];   // (2048, 512)
    const float* ent = (const float*)d_in[1];   // (40000, 512)
    const float* cb  = (const float*)d_in[2];   // (2048, 512)
    float* out = (float*)d_out;                 // score | vq_loss | idx

    cudaFuncSetAttribute(k_dist, cudaFuncAttributeMaxDynamicSharedMemorySize, DIST_SMEM);
    cudaFuncSetAttribute(k_sall, cudaFuncAttributeMaxDynamicSharedMemorySize, DIST_SMEM);
    cudaFuncSetAttribute(k_gather, cudaFuncAttributeMaxDynamicSharedMemorySize, GATHER_SMEM);

    k_splitrow<<<(NB + 7) / 8, 256>>>(ent, NB, 0);
    k_splitrow<<<(NK + 7) / 8, 256>>>(cb, NK, 1);
    k_splitrow<<<(NQ + 7) / 8, 256>>>(qry, NQ, 2);
    k_dist<<<313, 512, DIST_SMEM>>>(out);
    k_repair<<<64, 256>>>(ent, cb, out);
    k_sall<<<dim3(16, 16), 512, DIST_SMEM>>>();
    k_loss_final<<<1, 256>>>(out);
    k_gather<<<128, 512, GATHER_SMEM>>>(out);
}

// round 5
// speedup vs baseline: 1.4823x; 1.1742x over previous
#include <cuda_runtime.h>
#include <cuda_fp16.h>
#include <cstdint>

#define NQ 2048
#define NB 40000
#define NK 2048
#define ND 512
#define RT 64            // dist/sall CTA row-tile
#define STG 49152        // stage bytes: A0 8K | A1 8K | B0 16K | B1 16K

// ======================= device scratch (no allocation allowed) ==========
__device__ float g_c2[NK];
__device__ float g_x2[NB];
__device__ float g_bestd[NB];
__device__ int g_idx[NB];
__device__ __align__(16) float g_sall[(size_t)NQ * NK];   // 16 MB
__device__ int g_nflag;
__device__ int g_flag[4096];
__device__ __half g_eh0[(size_t)NB * ND];
__device__ __half g_eh1[(size_t)NB * ND];
__device__ __half g_ch0[(size_t)NK * ND];
__device__ __half g_ch1[(size_t)NK * ND];
__device__ __half g_qh0[(size_t)NQ * ND];
__device__ __half g_qh1[(size_t)NQ * ND];

// ======================= helpers =========================================
__device__ __forceinline__ uint32_t smem_to_u32(const void* p) {
    uint32_t a;
    asm("{ .reg .u64 t; cvta.to.shared.u64 t, %1; cvt.u32.u64 %0, t; }" : "=r"(a) : "l"(p));
    return a;
}
__device__ __forceinline__ void ldsm4(uint32_t* d, uint32_t addr) {
    asm volatile("ldmatrix.sync.aligned.m8n8.x4.shared.b16 {%0,%1,%2,%3}, [%4];"
        : "=r"(d[0]), "=r"(d[1]), "=r"(d[2]), "=r"(d[3]) : "r"(addr));
}
__device__ __forceinline__ void mma16816(float* c, const uint32_t* a, const uint32_t* b) {
    asm volatile("mma.sync.aligned.m16n8k16.row.col.f32.f16.f16.f32 "
        "{%0,%1,%2,%3}, {%4,%5,%6,%7}, {%8,%9}, {%0,%1,%2,%3};"
        : "+f"(c[0]), "+f"(c[1]), "+f"(c[2]), "+f"(c[3])
        : "r"(a[0]), "r"(a[1]), "r"(a[2]), "r"(a[3]), "r"(b[0]), "r"(b[1]));
}
__device__ __forceinline__ void cpa16(uint32_t dst, const void* src) {
    asm volatile("cp.async.cg.shared.global [%0], [%1], 16;" :: "r"(dst), "l"(src));
}
#define CPA_COMMIT() asm volatile("cp.async.commit_group;" ::: "memory")
#define CPA_WAIT1()  asm volatile("cp.async.wait_group 1;" ::: "memory")
#define CPA_WAIT0()  asm volatile("cp.async.wait_group 0;" ::: "memory")

// 256-thread tile issue: A planes 64x64 half, B planes 128x64 half, SW swizzle
__device__ __forceinline__ void issue_tiles(uint32_t base,
        const __half* a0, const __half* a1, const __half* b0, const __half* b1,
        size_t arow, size_t brow, int koff) {
    const int tid = threadIdx.x;
    #pragma unroll
    for (int i = 0; i < 2; i++) {
        int idx = tid + i * 256;
        int r = idx >> 3, c16 = idx & 7;
        uint32_t soff = (uint32_t)(r * 128 + ((c16 * 16) ^ ((r & 7) * 16)));
        size_t off = arow + (size_t)r * ND + koff + c16 * 8;
        cpa16(base + soff,         a0 + off);
        cpa16(base + 8192u + soff, a1 + off);
    }
    #pragma unroll
    for (int i = 0; i < 4; i++) {
        int idx = tid + i * 256;
        int r = idx >> 3, c16 = idx & 7;
        uint32_t soff = (uint32_t)(r * 128 + ((c16 * 16) ^ ((r & 7) * 16)));
        size_t off = brow + (size_t)r * ND + koff + c16 * 8;
        cpa16(base + 16384u + soff, b0 + off);
        cpa16(base + 32768u + soff, b1 + off);
    }
}

// one 64-K-chunk of 3-product emulated MMA (warp tile m32 n32)
__device__ __forceinline__ void mma_chunk(uint32_t base,
        const uint32_t* a_off, const uint32_t* b_off,
        int a_c0, int a_xr, int b_c0, int b_xr, float acc[2][4][4]) {
    #pragma unroll
    for (int kb = 0; kb < 4; kb++) {
        const uint32_t ca = (uint32_t)((a_c0 + kb * 32) ^ a_xr);
        const uint32_t cbo = (uint32_t)((b_c0 + kb * 32) ^ b_xr);
        uint32_t af[2][4], bf[4][2], bg[4][2];
        #pragma unroll
        for (int bp = 0; bp < 2; bp++) {
            uint32_t t[4];
            ldsm4(t, base + b_off[bp] + cbo);
            bf[bp * 2][0] = t[0]; bf[bp * 2][1] = t[1];
            bf[bp * 2 + 1][0] = t[2]; bf[bp * 2 + 1][1] = t[3];
        }
        #pragma unroll
        for (int bp = 0; bp < 2; bp++) {
            uint32_t t[4];
            ldsm4(t, base + b_off[bp] + 16384u + cbo);
            bg[bp * 2][0] = t[0]; bg[bp * 2][1] = t[1];
            bg[bp * 2 + 1][0] = t[2]; bg[bp * 2 + 1][1] = t[3];
        }
        #pragma unroll
        for (int am = 0; am < 2; am++) ldsm4(af[am], base + a_off[am] + ca);
        #pragma unroll
        for (int am = 0; am < 2; am++)
            #pragma unroll
            for (int an = 0; an < 4; an++) mma16816(acc[am][an], af[am], bf[an]);
        #pragma unroll
        for (int am = 0; am < 2; am++)
            #pragma unroll
            for (int an = 0; an < 4; an++) mma16816(acc[am][an], af[am], bg[an]);
        #pragma unroll
        for (int am = 0; am < 2; am++) ldsm4(af[am], base + a_off[am] + 8192u + ca);
        #pragma unroll
        for (int am = 0; am < 2; am++)
            #pragma unroll
            for (int an = 0; an < 4; an++) mma16816(acc[am][an], af[am], bf[an]);
    }
}

// ======================= fused row split + norms =========================
__global__ void k_splitrow(const float* __restrict__ src, int nrows, int which) {
    int gw = (blockIdx.x * 256 + threadIdx.x) >> 5;
    int lane = threadIdx.x & 31;
    if (which == 1 && gw == 0 && lane == 0) g_nflag = 0;
    if (gw >= nrows) return;
    const float* row = src + (size_t)gw * ND;
    __half *h0, *h1;
    if (which == 0) { h0 = g_eh0; h1 = g_eh1; }
    else if (which == 1) { h0 = g_ch0; h1 = g_ch1; }
    else { h0 = g_qh0; h1 = g_qh1; }
    float s = 0.f;
    #pragma unroll
    for (int j = 0; j < 4; j++) {
        int d = lane * 4 + j * 128;
        float4 v = *(const float4*)(row + d);
        __half a0 = __float2half_rn(v.x), a1 = __float2half_rn(v.y);
        __half a2 = __float2half_rn(v.z), a3 = __float2half_rn(v.w);
        __half b0 = __float2half_rn(v.x - __half2float(a0));
        __half b1 = __float2half_rn(v.y - __half2float(a1));
        __half b2 = __float2half_rn(v.z - __half2float(a2));
        __half b3 = __float2half_rn(v.w - __half2float(a3));
        __half2* p0 = (__half2*)(h0 + (size_t)gw * ND + d);
        __half2* p1 = (__half2*)(h1 + (size_t)gw * ND + d);
        p0[0] = __halves2half2(a0, a1); p0[1] = __halves2half2(a2, a3);
        p1[0] = __halves2half2(b0, b1); p1[1] = __halves2half2(b2, b3);
        s += v.x * v.x + v.y * v.y + v.z * v.z + v.w * v.w;
    }
    #pragma unroll
    for (int o = 16; o > 0; o >>= 1) s += __shfl_xor_sync(0xffffffffu, s, o);
    if (lane == 0) {
        if (which == 0) g_x2[gw] = s;
        else if (which == 1) g_c2[gw] = s;
    }
}

// ======================= HMMA distance + fused argmin ====================
// 625 CTAs x 64 rows, 256 threads (8 warps 2m x 4n), 2-stage, 2 CTAs/SM.
#define DIST_SMEM (2 * STG)

__global__ __launch_bounds__(256, 2)
void k_dist(float* __restrict__ out) {
    extern __shared__ char smem[];
    const uint32_t sb = smem_to_u32(smem);
    const int tid = threadIdx.x;
    const int wid = tid >> 5, lane = tid & 31;
    const int warp_m = wid >> 2, warp_n = wid & 3;
    const int row0 = blockIdx.x * RT;
    const size_t arow = (size_t)row0 * ND;

    const int a_row = lane & 15;
    const int a_c0 = (lane >> 4) * 16;
    const int a_xr = (a_row & 7) * 16;
    const int b_row = (lane & 7) + ((lane >> 4) << 3);
    const int b_c0 = ((lane >> 3) & 1) * 16;
    const int b_xr = (b_row & 7) * 16;
    uint32_t a_off[2], b_off[2];
    #pragma unroll
    for (int am = 0; am < 2; am++)
        a_off[am] = (uint32_t)((warp_m * 32 + am * 16 + a_row) * 128);
    #pragma unroll
    for (int bp = 0; bp < 2; bp++)
        b_off[bp] = 16384u + (uint32_t)((warp_n * 32 + bp * 16 + b_row) * 128);

    float best[4], best2[4]; int bidx[4];
    #pragma unroll
    for (int k = 0; k < 4; k++) { best[k] = 3.4e38f; best2[k] = 3.4e38f; bidx[k] = 0; }
    float acc[2][4][4];

    issue_tiles(sb, g_eh0, g_eh1, g_ch0, g_ch1, arow, 0, 0);
    CPA_COMMIT();

    for (int s = 0; s < 128; s++) {
        const int nt = s >> 3, kc = s & 7;
        if (s < 127) {
            const int s1 = s + 1;
            issue_tiles(sb + (uint32_t)(s1 & 1) * STG, g_eh0, g_eh1, g_ch0, g_ch1,
                        arow, (size_t)((s1 >> 3) * 128) * ND, (s1 & 7) * 64);
            CPA_COMMIT();
            CPA_WAIT1();
        } else {
            CPA_WAIT0();
        }
        __syncthreads();
        if (kc == 0) {
            #pragma unroll
            for (int am = 0; am < 2; am++)
                #pragma unroll
                for (int an = 0; an < 4; an++)
                    #pragma unroll
                    for (int r = 0; r < 4; r++) acc[am][an][r] = 0.f;
        }
        mma_chunk(sb + (uint32_t)(s & 1) * STG, a_off, b_off, a_c0, a_xr, b_c0, b_xr, acc);
        if (kc == 7) {
            #pragma unroll
            for (int am = 0; am < 2; am++) {
                #pragma unroll
                for (int an = 0; an < 4; an++) {
                    int cl = warp_n * 32 + an * 8 + (lane & 3) * 2;
                    float c2a = __ldg(&g_c2[nt * 128 + cl]);
                    float c2b = __ldg(&g_c2[nt * 128 + cl + 1]);
                    int gc = nt * 128 + cl;
                    #pragma unroll
                    for (int h = 0; h < 2; h++) {
                        int k = am * 2 + h;
                        float d0 = c2a - 2.f * acc[am][an][h * 2 + 0];
                        float d1 = c2b - 2.f * acc[am][an][h * 2 + 1];
                        if (d0 < best[k]) { best2[k] = best[k]; best[k] = d0; bidx[k] = gc; }
                        else if (d0 < best2[k]) best2[k] = d0;
                        if (d1 < best[k]) { best2[k] = best[k]; best[k] = d1; bidx[k] = gc + 1; }
                        else if (d1 < best2[k]) best2[k] = d1;
                    }
                }
            }
        }
        __syncthreads();
    }

    // ---- final reduce: quad lanes -> smem -> per-row ----
    float* sred1 = (float*)smem;
    float* sred2 = (float*)(smem + 1024);
    int*   sredi = (int*)(smem + 2048);
    #pragma unroll
    for (int k = 0; k < 4; k++) {
        float b1 = best[k], b2 = best2[k]; int ix = bidx[k];
        #pragma unroll
        for (int s = 1; s < 4; s <<= 1) {
            float o1 = __shfl_xor_sync(0xffffffffu, b1, s);
            float o2 = __shfl_xor_sync(0xffffffffu, b2, s);
            int oi = __shfl_xor_sync(0xffffffffu, ix, s);
            if (o1 < b1) { b2 = fminf(b1, o2); b1 = o1; ix = oi; }
            else b2 = fminf(b2, o1);
        }
        if ((lane & 3) == 0) {
            int rl = warp_m * 32 + (k >> 1) * 16 + (k & 1) * 8 + (lane >> 2);
            sred1[rl * 4 + warp_n] = b1;
            sred2[rl * 4 + warp_n] = b2;
            sredi[rl * 4 + warp_n] = ix;
        }
    }
    __syncthreads();
    if (tid < RT) {
        float b1 = sred1[tid * 4], b2 = sred2[tid * 4];
        int ix = sredi[tid * 4];
        #pragma unroll
        for (int w = 1; w < 4; w++) {
            float o1 = sred1[tid * 4 + w], o2 = sred2[tid * 4 + w];
            int oi = sredi[tid * 4 + w];
            if (o1 < b1) { b2 = fminf(b1, o2); b1 = o1; ix = oi; }
            else b2 = fminf(b2, o1);
        }
        int row = row0 + tid;
        g_idx[row] = ix;
        g_bestd[row] = b1;
        out[(size_t)NQ * NB + 1 + row] = (float)ix;
        if (b2 - b1 < 0.01f) {
            int s = atomicAdd(&g_nflag, 1);
            if (s < 4096) g_flag[s] = row;
        }
    }
}

// ======================= exact fp32 repair for near-ties =================
__global__ __launch_bounds__(256)
void k_repair(const float* __restrict__ ent, const float* __restrict__ cb,
              float* __restrict__ out) {
    __shared__ float sx[ND];
    __shared__ unsigned long long red[256];
    const int tid = threadIdx.x;
    int n = g_nflag;
    if (n > 4096) n = 4096;
    for (int f = blockIdx.x; f < n; f += gridDim.x) {
        const int b = g_flag[f];
        sx[tid] = ent[(size_t)b * ND + tid];
        sx[tid + 256] = ent[(size_t)b * ND + tid + 256];
        __syncthreads();
        float best = 3.4e38f;
        int bj = 0;
        const int j0 = tid * 8;
        for (int jj = 0; jj < 8; jj++) {
            const int j = j0 + jj;
            const float* c = cb + (size_t)j * ND;
            float dot = 0.f;
            #pragma unroll 8
            for (int d = 0; d < ND; d++) dot = fmaf(sx[d], c[d], dot);
            float d2 = g_c2[j] - 2.0f * dot;
            if (d2 < best) { best = d2; bj = j; }
        }
        unsigned int kb = __float_as_uint(best);
        kb = (kb & 0x80000000u) ? ~kb : (kb | 0x80000000u);
        red[tid] = ((unsigned long long)kb << 32) | (unsigned int)bj;
        __syncthreads();
        for (int o = 128; o > 0; o >>= 1) {
            if (tid < o) { unsigned long long v = red[tid + o]; if (v < red[tid]) red[tid] = v; }
            __syncthreads();
        }
        if (tid == 0) {
            unsigned long long w = red[0];
            int j = (int)(unsigned int)(w & 0xFFFFFFFFull);
            unsigned int kk = (unsigned int)(w >> 32);
            unsigned int fb = (kk & 0x80000000u) ? (kk & 0x7FFFFFFFu) : ~kk;
            g_idx[b] = j;
            g_bestd[b] = __uint_as_float(fb);
            out[(size_t)NQ * NB + 1 + b] = (float)j;
        }
        __syncthreads();
    }
}

// ======================= S_all = query @ codebook^T (HMMA) ===============
__global__ __launch_bounds__(256, 2)
void k_sall() {
    extern __shared__ char smem[];
    const uint32_t sb = smem_to_u32(smem);
    const int tid = threadIdx.x;
    const int wid = tid >> 5, lane = tid & 31;
    const int warp_m = wid >> 2, warp_n = wid & 3;
    const int col0 = blockIdx.x * 128;
    const int row0 = blockIdx.y * RT;
    const size_t arow = (size_t)row0 * ND;
    const size_t brow = (size_t)col0 * ND;

    const int a_row = lane & 15;
    const int a_c0 = (lane >> 4) * 16;
    const int a_xr = (a_row & 7) * 16;
    const int b_row = (lane & 7) + ((lane >> 4) << 3);
    const int b_c0 = ((lane >> 3) & 1) * 16;
    const int b_xr = (b_row & 7) * 16;
    uint32_t a_off[2], b_off[2];
    #pragma unroll
    for (int am = 0; am < 2; am++)
        a_off[am] = (uint32_t)((warp_m * 32 + am * 16 + a_row) * 128);
    #pragma unroll
    for (int bp = 0; bp < 2; bp++)
        b_off[bp] = 16384u + (uint32_t)((warp_n * 32 + bp * 16 + b_row) * 128);

    float acc[2][4][4];
    #pragma unroll
    for (int am = 0; am < 2; am++)
        #pragma unroll
        for (int an = 0; an < 4; an++)
            #pragma unroll
            for (int r = 0; r < 4; r++) acc[am][an][r] = 0.f;

    issue_tiles(sb, g_qh0, g_qh1, g_ch0, g_ch1, arow, brow, 0);
    CPA_COMMIT();

    for (int s = 0; s < 8; s++) {
        if (s < 7) {
            issue_tiles(sb + (uint32_t)((s + 1) & 1) * STG, g_qh0, g_qh1, g_ch0, g_ch1,
                        arow, brow, (s + 1) * 64);
            CPA_COMMIT();
            CPA_WAIT1();
        } else {
            CPA_WAIT0();
        }
        __syncthreads();
        mma_chunk(sb + (uint32_t)(s & 1) * STG, a_off, b_off, a_c0, a_xr, b_c0, b_xr, acc);
        __syncthreads();
    }

    #pragma unroll
    for (int am = 0; am < 2; am++)
        #pragma unroll
        for (int h = 0; h < 2; h++) {
            int r = row0 + warp_m * 32 + am * 16 + h * 8 + (lane >> 2);
            #pragma unroll
            for (int an = 0; an < 4; an++) {
                int c = col0 + warp_n * 32 + an * 8 + (lane & 3) * 2;
                *(float2*)(g_sall + (size_t)r * NK + c) =
                    make_float2(acc[am][an][h * 2], acc[am][an][h * 2 + 1]);
            }
        }
}

// ======================= vq_loss: mean(x2 + bestd) * 1.25 ================
__global__ void k_loss_final(float* __restrict__ out) {
    __shared__ double sred[256];
    const int tid = threadIdx.x;
    double s = 0.0;
    for (int b = tid; b < NB; b += 256) s += (double)g_x2[b] + (double)g_bestd[b];
    sred[tid] = s;
    __syncthreads();
    for (int o = 128; o > 0; o >>= 1) {
        if (tid < o) sred[tid] += sred[tid + o];
        __syncthreads();
    }
    if (tid == 0) out[(size_t)NQ * NB] = (float)(1.25 * sred[0] / ((double)NB * (double)ND));
}

// ======================= score gather ====================================
#define QCH 8
#define GATHER_SMEM (QCH * NK * 4)
__global__ __launch_bounds__(512)
void k_gather(float* __restrict__ out) {
    extern __shared__ float srow[];   // [QCH][NK]
    const int tid = threadIdx.x;
    const int q0 = blockIdx.x * QCH;
    for (int i = tid; i < QCH * NK / 4; i += 512)
        ((float4*)srow)[i] = ((const float4*)(g_sall + (size_t)q0 * NK))[i];
    __syncthreads();
    for (int c = 0; c < 10; c++) {
        int b = c * 4096 + tid * 8;
        if (b >= NB) continue;
        int idx8[8];
        #pragma unroll
        for (int t = 0; t < 8; t++) idx8[t] = g_idx[b + t];
        #pragma unroll
        for (int q = 0; q < QCH; q++) {
            const float* r = srow + q * NK;
            float4 v0 = make_float4(r[idx8[0]], r[idx8[1]], r[idx8[2]], r[idx8[3]]);
            float4 v1 = make_float4(r[idx8[4]], r[idx8[5]], r[idx8[6]], r[idx8[7]]);
            float* p = out + (size_t)(q0 + q) * NB + b;
            *(float4*)p = v0;
            *(float4*)(p + 4) = v1;
        }
    }
}

// ======================= launch ==========================================
extern "C" void kernel_launch(void* const* d_in, const int* in_sizes, int n_in,
                              void* d_out, int out_size) {
    const float* qry = (const float*)d_in[0];   // (2048, 512)
    const float* ent = (const float*)d_in[1];   // (40000, 512)
    const float* cb  = (const float*)d_in[2];   // (2048, 512)
    float* out = (float*)d_out;                 // score | vq_loss | idx

    cudaFuncSetAttribute(k_dist, cudaFuncAttributeMaxDynamicSharedMemorySize, DIST_SMEM);
    cudaFuncSetAttribute(k_sall, cudaFuncAttributeMaxDynamicSharedMemorySize, DIST_SMEM);
    cudaFuncSetAttribute(k_gather, cudaFuncAttributeMaxDynamicSharedMemorySize, GATHER_SMEM);

    k_splitrow<<<(NB + 7) / 8, 256>>>(ent, NB, 0);
    k_splitrow<<<(NK + 7) / 8, 256>>>(cb, NK, 1);
    k_splitrow<<<(NQ + 7) / 8, 256>>>(qry, NQ, 2);
    k_dist<<<625, 256, DIST_SMEM>>>(out);
    k_repair<<<512, 256>>>(ent, cb, out);
    k_sall<<<dim3(16, 32), 256, DIST_SMEM>>>();
    k_loss_final<<<1, 256>>>(out);
    k_gather<<<256, 512, GATHER_SMEM>>>(out);
}